// round 16
// baseline (speedup 1.0000x reference)
#include <cuda_runtime.h>
#include <cuda_bf16.h>
#include <cuda_fp16.h>
#include <math.h>
#include <stdint.h>

#define BATCH 4
#define SEQ   2048
#define DIM   512
#define UDIM  256
#define MROWS (BATCH*SEQ)

// ---------------- scratch (device globals) ---------------------------------
__device__ __align__(128) unsigned char g_xps [(size_t)MROWS*DIM*4];
__device__ __align__(128) unsigned char g_wps [(size_t)3*UDIM*DIM*4];
__device__ __align__(128) unsigned char g_qps [(size_t)MROWS*UDIM*4];
__device__ __align__(128) unsigned char g_kps [(size_t)MROWS*UDIM*4];
__device__ __align__(128) float         g_v   [(size_t)MROWS*UDIM];
__device__ __align__(128) unsigned char g_vth [(size_t)BATCH*UDIM*SEQ*2];  // fp16 [U,S]
__device__ __align__(128) unsigned char g_ph  [(size_t)MROWS*SEQ*2];       // fp16 P (tile-shifted)
__device__ __align__(128) float2        g_part[(size_t)MROWS*16];

// ---------------- helpers ---------------------------------------------------
__device__ __forceinline__ uint32_t smem_u32(const void* p){
    uint32_t a;
    asm("{ .reg .u64 t; cvta.to.shared.u64 t, %1; cvt.u32.u64 %0, t; }" : "=r"(a) : "l"(p));
    return a;
}
__device__ __forceinline__ uint32_t sw128(uint32_t off){ return off ^ ((off>>3)&0x70); }

__device__ __forceinline__ uint32_t packh(float a, float b){
    __half2 h = __floats2half2_rn(a, b);
    return *reinterpret_cast<uint32_t*>(&h);
}
// fp16 limb split: hi = fp16(x), lo = fp16(x - hi)
__device__ __forceinline__ void split2(float a, float b, uint32_t& hi, uint32_t& lo){
    __half ha = __float2half_rn(a), hb = __float2half_rn(b);
    hi = packh(__half2float(ha), __half2float(hb));
    lo = packh(a - __half2float(ha), b - __half2float(hb));
}
__device__ __forceinline__ void split4(float4 v, uint2& hi, uint2& lo){
    split2(v.x, v.y, hi.x, lo.x);
    split2(v.z, v.w, hi.y, lo.y);
}
__device__ __forceinline__ uint32_t hmul2u(uint32_t a, uint32_t b){
    uint32_t r;
    asm("mul.rn.f16x2 %0, %1, %2;" : "=r"(r) : "r"(a), "r"(b));
    return r;
}

// fast exp for x <= 0, FMA/ALU pipes only
__device__ __forceinline__ float fexp(float x){
    float t = x * 1.44269504088896f;
    t = fmaxf(t, -120.f);
    float rn = t + 12582912.f;
    int   ki = (__float_as_int(rn) & 0x7FFFFF) - 0x400000;
    float f  = t - (rn - 12582912.f);
    float p = fmaf(f, 0.00961812910762848f, 0.0555041086648216f);
    p = fmaf(f, p, 0.240226506959101f);
    p = fmaf(f, p, 0.693147180559945f);
    p = fmaf(f, p, 1.0f);
    return __int_as_float(__float_as_int(p) + (ki << 23));
}

__device__ __forceinline__ void cpa16(uint32_t dst, const void* src){
    asm volatile("cp.async.cg.shared.global [%0], [%1], 16;" :: "r"(dst), "l"(src));
}
__device__ __forceinline__ void cpa_commit(){ asm volatile("cp.async.commit_group;" ::: "memory"); }
template<int N> __device__ __forceinline__ void cpa_wait(){
    asm volatile("cp.async.wait_group %0;" :: "n"(N) : "memory");
}
__device__ __forceinline__ void ldm_x4(uint32_t* r, uint32_t addr){
    asm volatile("ldmatrix.sync.aligned.m8n8.x4.shared.b16 {%0,%1,%2,%3}, [%4];"
                 : "=r"(r[0]), "=r"(r[1]), "=r"(r[2]), "=r"(r[3]) : "r"(addr));
}
// fp16 inputs, fp32 accumulator
#define MMA16816H(d, a, b0v, b1v) \
    asm volatile("mma.sync.aligned.m16n8k16.row.col.f32.f16.f16.f32 " \
                 "{%0,%1,%2,%3},{%4,%5,%6,%7},{%8,%9},{%0,%1,%2,%3};" \
                 : "+f"((d)[0]), "+f"((d)[1]), "+f"((d)[2]), "+f"((d)[3]) \
                 : "r"((a)[0]), "r"((a)[1]), "r"((a)[2]), "r"((a)[3]), \
                   "r"(b0v), "r"(b1v))
// fp16 inputs, fp16 accumulator (2 regs = 4 halves)
#define MMA16816HH(d2, a, b0v, b1v) \
    asm volatile("mma.sync.aligned.m16n8k16.row.col.f16.f16.f16.f16 " \
                 "{%0,%1},{%2,%3,%4,%5},{%6,%7},{%0,%1};" \
                 : "+r"((d2)[0]), "+r"((d2)[1]) \
                 : "r"((a)[0]), "r"((a)[1]), "r"((a)[2]), "r"((a)[3]), \
                   "r"(b0v), "r"(b1v))

// hh in f32 acc; (hi*lo + lo*hi) into shared f16 acc
#define MMA_BLOCK(acc, acch, ah, al, bh, bl) \
    { \
        _Pragma("unroll") \
        for (int mt = 0; mt < 2; mt++) { _Pragma("unroll") \
            for (int nt = 0; nt < 4; nt++) { \
                const int np = nt >> 1, ix = (nt & 1) * 2; \
                MMA16816H(acc[mt][nt], ah[mt], bh[np][ix], bh[np][ix+1]); } } \
        _Pragma("unroll") \
        for (int mt = 0; mt < 2; mt++) { _Pragma("unroll") \
            for (int nt = 0; nt < 4; nt++) { \
                const int np = nt >> 1, ix = (nt & 1) * 2; \
                MMA16816HH(acch[mt][nt], ah[mt], bl[np][ix], bl[np][ix+1]); } } \
        _Pragma("unroll") \
        for (int mt = 0; mt < 2; mt++) { _Pragma("unroll") \
            for (int nt = 0; nt < 4; nt++) { \
                const int np = nt >> 1, ix = (nt & 1) * 2; \
                MMA16816HH(acch[mt][nt], al[mt], bh[np][ix], bh[np][ix+1]); } } \
    }

// ---------------- generic fp16x3 ps GEMM ------------------------------------
// MODE 3: QKV router. MODE 2: scores -> fp16 P_tile = exp(s - m_tile) + stats.
#define STAGES    4
#define STG_BYTES 16384
#define SMEM_GEMM (STAGES*2*STG_BYTES)   // 128 KB

template<int MODE>
__global__ __launch_bounds__(512)
void gemm_ps(const unsigned char* __restrict__ A, const unsigned char* __restrict__ B,
             unsigned char* __restrict__ Cp, unsigned char* __restrict__ Cq,
             unsigned char* __restrict__ Ck, float* __restrict__ Cv,
             float2* __restrict__ part,
             int K, int pitchA, int pitchB,
             size_t sA, size_t sB)
{
    extern __shared__ char smem[];
    __shared__ float2 stat_sm[4][32][4];
    __shared__ float  m_comb[4][32];
    A += (size_t)blockIdx.z * sA;
    B += (size_t)blockIdx.z * sB;

    const int tid = threadIdx.x;
    const int wid = tid >> 5, lt = tid & 31;
    const int warpM = (wid & 3) * 32, warpN = (wid >> 2) * 32;
    const int rowBase = blockIdx.y * 128, colBase = blockIdx.x * 128;

    const int lr = tid >> 2;
    const int lg = (tid & 3) * 32;
    const uint32_t mask = (uint32_t)(lr & 7) * 16;
    const uint32_t o1 = (uint32_t)lr * 128 + ((uint32_t)lg ^ mask);
    const uint32_t o2 = o1 ^ 16;
    const unsigned char* gA = A + (size_t)(rowBase + lr) * pitchA + lg;
    const unsigned char* gB = B + (size_t)(colBase + lr) * pitchB + lg;

    const uint32_t sb = smem_u32(smem);
    const int nch = K / 32;

    const uint32_t aOff = (uint32_t)((warpM + (lt & 15)) * 128 + ((lt >> 4) & 1) * 16);
    const uint32_t bOff = (uint32_t)((warpN + (lt & 7) + ((lt >> 4) & 1) * 8) * 128
                                     + ((lt >> 3) & 1) * 16);

    float acc[2][4][4];
    uint32_t acch[2][4][2];
    #pragma unroll
    for (int i = 0; i < 2; i++)
        #pragma unroll
        for (int j = 0; j < 4; j++) {
            #pragma unroll
            for (int e = 0; e < 4; e++) acc[i][j][e] = 0.f;
            acch[i][j][0] = 0u; acch[i][j][1] = 0u;
        }

    #pragma unroll
    for (int st = 0; st < 3; st++) {
        uint32_t base = sb + (uint32_t)st * (2*STG_BYTES);
        const unsigned char* pa = gA + (size_t)st * 128;
        const unsigned char* pb = gB + (size_t)st * 128;
        cpa16(base + o1, pa);                 cpa16(base + o2, pa + 16);
        cpa16(base + STG_BYTES + o1, pb);     cpa16(base + STG_BYTES + o2, pb + 16);
        cpa_commit();
    }

    for (int c = 0; c < nch; c++) {
        cpa_wait<2>();
        __syncthreads();

        if (c + 3 < nch) {
            uint32_t base = sb + (uint32_t)((c + 3) & 3) * (2*STG_BYTES);
            const unsigned char* pa = gA + (size_t)(c + 3) * 128;
            const unsigned char* pb = gB + (size_t)(c + 3) * 128;
            cpa16(base + o1, pa);                 cpa16(base + o2, pa + 16);
            cpa16(base + STG_BYTES + o1, pb);     cpa16(base + STG_BYTES + o2, pb + 16);
        }
        cpa_commit();

        const uint32_t aB = sb + (uint32_t)(c & 3) * (2*STG_BYTES);
        const uint32_t bB = aB + STG_BYTES;

        #pragma unroll
        for (int s = 0; s < 2; s++) {
            uint32_t ah[2][4], al[2][4], bh[2][4], bl[2][4];
            #pragma unroll
            for (int mt = 0; mt < 2; mt++) {
                uint32_t o = aOff + (uint32_t)mt * 2048 + (uint32_t)s * 32;
                ldm_x4(ah[mt], aB + sw128(o));
                ldm_x4(al[mt], aB + sw128(o + 64));
            }
            #pragma unroll
            for (int np = 0; np < 2; np++) {
                uint32_t o = bOff + (uint32_t)np * 2048 + (uint32_t)s * 32;
                ldm_x4(bh[np], bB + sw128(o));
                ldm_x4(bl[np], bB + sw128(o + 64));
            }
            MMA_BLOCK(acc, acch, ah, al, bh, bl);
        }
    }

    // fold f16 cross-term accumulators into f32 acc
    #pragma unroll
    for (int mt = 0; mt < 2; mt++)
        #pragma unroll
        for (int nt = 0; nt < 4; nt++) {
            float2 c01 = __half22float2(*reinterpret_cast<__half2*>(&acch[mt][nt][0]));
            float2 c23 = __half22float2(*reinterpret_cast<__half2*>(&acch[mt][nt][1]));
            acc[mt][nt][0] += c01.x;  acc[mt][nt][1] += c01.y;
            acc[mt][nt][2] += c23.x;  acc[mt][nt][3] += c23.y;
        }

    if (MODE == 3) {
        #pragma unroll
        for (int mt = 0; mt < 2; mt++) {
            const int r0 = rowBase + warpM + mt * 16 + (lt >> 2);
            #pragma unroll
            for (int nt = 0; nt < 4; nt++) {
                const int col = colBase + warpN + nt * 8 + (lt & 3) * 2;
                if (col < 512) {
                    unsigned char* base = (col < 256) ? Cq : Ck;
                    const int cc = col & 255;
                    const uint32_t cb = (uint32_t)(cc >> 5) * 128 + (uint32_t)(cc & 31) * 2;
                    uint32_t hi, lo;
                    split2(acc[mt][nt][0], acc[mt][nt][1], hi, lo);
                    unsigned char* p0 = base + (size_t)r0 * (UDIM*4) + cb;
                    *(uint32_t*)p0        = hi;
                    *(uint32_t*)(p0 + 64) = lo;
                    split2(acc[mt][nt][2], acc[mt][nt][3], hi, lo);
                    unsigned char* p1 = base + (size_t)(r0 + 8) * (UDIM*4) + cb;
                    *(uint32_t*)p1        = hi;
                    *(uint32_t*)(p1 + 64) = lo;
                } else {
                    const int cc = col - 512;
                    *(float2*)&Cv[(size_t)r0 * UDIM + cc] =
                        make_float2(acc[mt][nt][0], acc[mt][nt][1]);
                    *(float2*)&Cv[(size_t)(r0 + 8) * UDIM + cc] =
                        make_float2(acc[mt][nt][2], acc[mt][nt][3]);
                }
            }
        }
        return;
    }

    if (MODE == 2) {
        // ---- per-(row, warpN-group) stats ----
        #pragma unroll
        for (int mt = 0; mt < 2; mt++) {
            #pragma unroll
            for (int half = 0; half < 2; half++) {
                float m = -INFINITY;
                #pragma unroll
                for (int nt = 0; nt < 4; nt++)
                    m = fmaxf(m, fmaxf(acc[mt][nt][half*2], acc[mt][nt][half*2+1]));
                float l = 0.f;
                #pragma unroll
                for (int nt = 0; nt < 4; nt++) {
                    l += __expf(acc[mt][nt][half*2]   - m);
                    l += __expf(acc[mt][nt][half*2+1] - m);
                }
                #pragma unroll
                for (int off = 1; off <= 2; off <<= 1) {
                    float om = __shfl_xor_sync(0xffffffffu, m, off);
                    float ol = __shfl_xor_sync(0xffffffffu, l, off);
                    float nm = fmaxf(m, om);
                    l = l * __expf(m - nm) + ol * __expf(om - nm);
                    m = nm;
                }
                if ((lt & 3) == 0) {
                    const int rloc = mt * 16 + half * 8 + (lt >> 2);
                    stat_sm[wid & 3][rloc][wid >> 2] = make_float2(m, l);
                }
            }
        }
        __syncthreads();
        if (tid < 128) {
            const int mw = tid >> 5, r = tid & 31;
            float2 a = stat_sm[mw][r][0];
            float m = a.x, l = a.y;
            #pragma unroll
            for (int j = 1; j < 4; j++) {
                float2 b = stat_sm[mw][r][j];
                float nm = fmaxf(m, b.x);
                l = l * __expf(m - nm) + b.y * __expf(b.x - nm);
                m = nm;
            }
            const size_t grow = (size_t)blockIdx.z * SEQ + rowBase + mw * 32 + r;
            part[grow * 16 + blockIdx.x] = make_float2(m, l);
            m_comb[mw][r] = m;
        }
        __syncthreads();

        // ---- write P_tile = exp(s - m_tile) as fp16 ----
        #pragma unroll
        for (int mt = 0; mt < 2; mt++) {
            const int rl0 = mt * 16 + (lt >> 2);
            const float m0 = m_comb[wid & 3][rl0];
            const float m1 = m_comb[wid & 3][rl0 + 8];
            const size_t gr0 = (size_t)blockIdx.z * SEQ + rowBase + warpM + rl0;
            #pragma unroll
            for (int nt = 0; nt < 4; nt++) {
                const int col = colBase + warpN + nt * 8 + (lt & 3) * 2;
                *(uint32_t*)(Cp + gr0 * (SEQ*2) + (size_t)col * 2) =
                    packh(fexp(acc[mt][nt][0] - m0), fexp(acc[mt][nt][1] - m0));
                *(uint32_t*)(Cp + (gr0 + 8) * (SEQ*2) + (size_t)col * 2) =
                    packh(fexp(acc[mt][nt][2] - m1), fexp(acc[mt][nt][3] - m1));
            }
        }
    }
}

// ---------------- fp16 PV GEMM with in-prologue shift + fused rescale -------
#define SCL_OFF   (STAGES*2*STG_BYTES)          // after the 128 KB stage ring
#define SMEM_H    (SCL_OFF + 128*17*4)          // + padded scale table (8.5 KB)

__global__ __launch_bounds__(512)
void gemm_h(const unsigned char* __restrict__ A, const unsigned char* __restrict__ B,
            float* __restrict__ C, const float2* __restrict__ part,
            int K, int pitchA, int pitchB, int ldC,
            size_t sA, size_t sB, size_t sC)
{
    extern __shared__ char smem[];
    A += (size_t)blockIdx.z * sA;
    B += (size_t)blockIdx.z * sB;
    C += (size_t)blockIdx.z * sC;
    part += (size_t)blockIdx.z * SEQ * 16;

    const int tid = threadIdx.x;
    const int wid = tid >> 5, lt = tid & 31;
    const int warpM = (wid & 3) * 32, warpN = (wid >> 2) * 32;
    const int rowBase = blockIdx.y * 128, colBase = blockIdx.x * 128;

    const int lr = tid >> 2;
    const int lg = (tid & 3) * 32;
    const uint32_t mask = (uint32_t)(lr & 7) * 16;
    const uint32_t o1 = (uint32_t)lr * 128 + ((uint32_t)lg ^ mask);
    const uint32_t o2 = o1 ^ 16;
    const unsigned char* gA = A + (size_t)(rowBase + lr) * pitchA + lg;
    const unsigned char* gB = B + (size_t)(colBase + lr) * pitchB + lg;

    const uint32_t sb = smem_u32(smem);
    const int nch = K / 64;

    const uint32_t aOff = (uint32_t)((warpM + (lt & 15)) * 128 + ((lt >> 4) & 1) * 16);
    const uint32_t bOff = (uint32_t)((warpN + (lt & 7) + ((lt >> 4) & 1) * 8) * 128
                                     + ((lt >> 3) & 1) * 16);

    float acc[2][4][4];
    #pragma unroll
    for (int i = 0; i < 2; i++)
        #pragma unroll
        for (int j = 0; j < 4; j++)
            #pragma unroll
            for (int e = 0; e < 4; e++) acc[i][j][e] = 0.f;

    #pragma unroll
    for (int st = 0; st < 3; st++) {
        uint32_t base = sb + (uint32_t)st * (2*STG_BYTES);
        const unsigned char* pa = gA + (size_t)st * 128;
        const unsigned char* pb = gB + (size_t)st * 128;
        cpa16(base + o1, pa);                 cpa16(base + o2, pa + 16);
        cpa16(base + STG_BYTES + o1, pb);     cpa16(base + STG_BYTES + o2, pb + 16);
        cpa_commit();
    }

    // ---- in-prologue shift + scale table (overlaps cp.async latency) ----
    {
        const int r = tid >> 2, q = tid & 3;
        const float2* pp = part + ((size_t)rowBase + r) * 16 + q * 4;
        float2 p0 = pp[0], p1 = pp[1], p2 = pp[2], p3 = pp[3];
        float m = fmaxf(fmaxf(p0.x, p1.x), fmaxf(p2.x, p3.x));
        m = fmaxf(m, __shfl_xor_sync(0xffffffffu, m, 1));
        m = fmaxf(m, __shfl_xor_sync(0xffffffffu, m, 2));
        float l = p0.y * __expf(p0.x - m) + p1.y * __expf(p1.x - m)
                + p2.y * __expf(p2.x - m) + p3.y * __expf(p3.x - m);
        l += __shfl_xor_sync(0xffffffffu, l, 1);
        l += __shfl_xor_sync(0xffffffffu, l, 2);
        const float sh = m + logf(l);
        float* srow = (float*)(smem + SCL_OFF) + r * 17 + q * 4;
        srow[0] = __expf(p0.x - sh);
        srow[1] = __expf(p1.x - sh);
        srow[2] = __expf(p2.x - sh);
        srow[3] = __expf(p3.x - sh);
    }

    uint32_t scl2[4];   // half2 broadcast scales: rows +0, +8, +16, +24

    for (int c = 0; c < nch; c++) {
        cpa_wait<2>();
        __syncthreads();   // also orders the scale-table writes (at c==0)

        if ((c & 1) == 0) {
            const int t = c >> 1;
            const float* ss = (const float*)(smem + SCL_OFF);
            const int rb = warpM + (lt >> 2);
            float f0  = ss[(rb +  0) * 17 + t];
            float f8  = ss[(rb +  8) * 17 + t];
            float f16 = ss[(rb + 16) * 17 + t];
            float f24 = ss[(rb + 24) * 17 + t];
            scl2[0] = packh(f0,  f0);
            scl2[1] = packh(f8,  f8);
            scl2[2] = packh(f16, f16);
            scl2[3] = packh(f24, f24);
        }

        if (c + 3 < nch) {
            uint32_t base = sb + (uint32_t)((c + 3) & 3) * (2*STG_BYTES);
            const unsigned char* pa = gA + (size_t)(c + 3) * 128;
            const unsigned char* pb = gB + (size_t)(c + 3) * 128;
            cpa16(base + o1, pa);                 cpa16(base + o2, pa + 16);
            cpa16(base + STG_BYTES + o1, pb);     cpa16(base + STG_BYTES + o2, pb + 16);
        }
        cpa_commit();

        const uint32_t aB = sb + (uint32_t)(c & 3) * (2*STG_BYTES);
        const uint32_t bB = aB + STG_BYTES;

        #pragma unroll
        for (int s = 0; s < 4; s++) {
            uint32_t ah[2][4], bh[2][4];
            #pragma unroll
            for (int mt = 0; mt < 2; mt++) {
                uint32_t o = aOff + (uint32_t)mt * 2048 + (uint32_t)s * 32;
                ldm_x4(ah[mt], aB + sw128(o));
                ah[mt][0] = hmul2u(ah[mt][0], scl2[mt*2]);
                ah[mt][2] = hmul2u(ah[mt][2], scl2[mt*2]);
                ah[mt][1] = hmul2u(ah[mt][1], scl2[mt*2+1]);
                ah[mt][3] = hmul2u(ah[mt][3], scl2[mt*2+1]);
            }
            #pragma unroll
            for (int np = 0; np < 2; np++) {
                uint32_t o = bOff + (uint32_t)np * 2048 + (uint32_t)s * 32;
                ldm_x4(bh[np], bB + sw128(o));
            }
            #pragma unroll
            for (int mt = 0; mt < 2; mt++)
                #pragma unroll
                for (int nt = 0; nt < 4; nt++) {
                    const int np = nt >> 1, ix = (nt & 1) * 2;
                    MMA16816H(acc[mt][nt], ah[mt], bh[np][ix], bh[np][ix+1]);
                }
        }
    }

    #pragma unroll
    for (int mt = 0; mt < 2; mt++) {
        const int r0 = rowBase + warpM + mt * 16 + (lt >> 2);
        #pragma unroll
        for (int nt = 0; nt < 4; nt++) {
            const int cc = colBase + warpN + nt * 8 + (lt & 3) * 2;
            *(float2*)&C[(size_t)r0 * ldC + cc] =
                make_float2(acc[mt][nt][0], acc[mt][nt][1]);
            *(float2*)&C[(size_t)(r0 + 8) * ldC + cc] =
                make_float2(acc[mt][nt][2], acc[mt][nt][3]);
        }
    }
}

// ---------------- split fp32 -> packed-split fp16 limbs ---------------------
__global__ __launch_bounds__(256)
void split_pack(const float* __restrict__ in, unsigned char* __restrict__ out, int Kelems)
{
    const size_t idx = ((size_t)blockIdx.x * 256 + threadIdx.x) * 8;
    const size_t row = idx / Kelems;
    const int k0 = (int)(idx % Kelems);
    float4 f0 = *(const float4*)(in + idx);
    float4 f1 = *(const float4*)(in + idx + 4);
    uint2 h0, l0, h1, l1;
    split4(f0, h0, l0);
    split4(f1, h1, l1);
    unsigned char* p = out + row * ((size_t)Kelems * 4) + (k0 >> 5) * 128 + (k0 & 31) * 2;
    *(uint4*)p        = make_uint4(h0.x, h0.y, h1.x, h1.y);
    *(uint4*)(p + 64) = make_uint4(l0.x, l0.y, l1.x, l1.y);
}

// ---------------- fused 3-weight transpose+split (fp16 limbs) ---------------
__global__ __launch_bounds__(256)
void transpose_split_w(const float* __restrict__ W0, const float* __restrict__ W1,
                       const float* __restrict__ W2, unsigned char* __restrict__ out)
{
    __shared__ float t[32][33];
    const float* in = (blockIdx.z == 0) ? W0 : (blockIdx.z == 1) ? W1 : W2;
    out += (size_t)blockIdx.z * ((size_t)UDIM * DIM * 4);
    const int tid = threadIdx.x;
    const int tx = tid & 31, ty = tid >> 5;
    int x = blockIdx.x * 32 + tx;
    int y = blockIdx.y * 32 + ty;
    #pragma unroll
    for (int j = 0; j < 32; j += 8)
        t[ty + j][tx] = in[(size_t)(y + j) * UDIM + x];
    __syncthreads();

    const int wr = tid >> 3;
    const int wg = tid & 7;
    uint32_t h0, l0, h1, l1;
    split2(t[wg*4 + 0][wr], t[wg*4 + 1][wr], h0, l0);
    split2(t[wg*4 + 2][wr], t[wg*4 + 3][wr], h1, l1);
    unsigned char* p = out + (size_t)(blockIdx.x * 32 + wr) * (DIM*4)
                           + (size_t)blockIdx.y * 128 + wg * 8;
    *(uint2*)p        = make_uint2(h0, h1);
    *(uint2*)(p + 64) = make_uint2(l0, l1);
}

// ---------------- V transpose: fp32 [S,U] -> fp16 [U,S] ---------------------
__global__ __launch_bounds__(256)
void transpose_h(const float* __restrict__ in, unsigned char* __restrict__ out,
                 size_t sIn, size_t sOut)
{
    __shared__ float t[32][33];
    in  += (size_t)blockIdx.z * sIn;
    out += (size_t)blockIdx.z * sOut;
    const int tid = threadIdx.x;
    const int tx = tid & 31, ty = tid >> 5;
    int x = blockIdx.x * 32 + tx;
    int y = blockIdx.y * 32 + ty;
    #pragma unroll
    for (int j = 0; j < 32; j += 8)
        t[ty + j][tx] = in[(size_t)(y + j) * UDIM + x];
    __syncthreads();

    const int wr = tid >> 3;
    const int wg = tid & 7;
    uint32_t h01 = packh(t[wg*4 + 0][wr], t[wg*4 + 1][wr]);
    uint32_t h23 = packh(t[wg*4 + 2][wr], t[wg*4 + 3][wr]);
    unsigned char* p = out + (size_t)(blockIdx.x * 32 + wr) * (SEQ*2)
                           + (size_t)blockIdx.y * 64 + wg * 8;
    *(uint2*)p = make_uint2(h01, h23);
}

// ---------------- launch ----------------------------------------------------
extern "C" void kernel_launch(void* const* d_in, const int* in_sizes, int n_in,
                              void* d_out, int out_size)
{
    const float* x  = (const float*)d_in[0];
    const float* Wq = (const float*)d_in[1];
    const float* Wk = (const float*)d_in[2];
    const float* Wv = (const float*)d_in[3];
    float* out = (float*)d_out;

    unsigned char *xps, *wps, *qps, *kps, *vth, *ph;
    float *v;
    float2 *part;
    cudaGetSymbolAddress((void**)&xps,  g_xps);
    cudaGetSymbolAddress((void**)&wps,  g_wps);
    cudaGetSymbolAddress((void**)&qps,  g_qps);
    cudaGetSymbolAddress((void**)&kps,  g_kps);
    cudaGetSymbolAddress((void**)&v,    g_v);
    cudaGetSymbolAddress((void**)&vth,  g_vth);
    cudaGetSymbolAddress((void**)&ph,   g_ph);
    cudaGetSymbolAddress((void**)&part, g_part);

    cudaFuncSetAttribute(gemm_ps<2>, cudaFuncAttributeMaxDynamicSharedMemorySize, SMEM_GEMM);
    cudaFuncSetAttribute(gemm_ps<3>, cudaFuncAttributeMaxDynamicSharedMemorySize, SMEM_GEMM);
    cudaFuncSetAttribute(gemm_h,     cudaFuncAttributeMaxDynamicSharedMemorySize, SMEM_H);

    static cudaStream_t sAux = nullptr;
    static cudaEvent_t evFork1 = nullptr, evJoin1 = nullptr,
                       evFork2 = nullptr, evJoin2 = nullptr;
    if (sAux == nullptr) {
        cudaStreamCreateWithFlags(&sAux, cudaStreamNonBlocking);
        cudaEventCreateWithFlags(&evFork1, cudaEventDisableTiming);
        cudaEventCreateWithFlags(&evJoin1, cudaEventDisableTiming);
        cudaEventCreateWithFlags(&evFork2, cudaEventDisableTiming);
        cudaEventCreateWithFlags(&evJoin2, cudaEventDisableTiming);
    }

    // ---- fork 1: weight prep (aux) || x split (main) ----
    cudaEventRecord(evFork1, 0);
    cudaStreamWaitEvent(sAux, evFork1, 0);
    transpose_split_w<<<dim3(UDIM/32, DIM/32, 3), 256, 0, sAux>>>(Wq, Wk, Wv, wps);
    cudaEventRecord(evJoin1, sAux);

    split_pack<<<(MROWS*DIM)/(256*8), 256>>>(x, xps, DIM);
    cudaStreamWaitEvent(0, evJoin1, 0);

    // ---- fused QKV with router epilogue (main) ----
    {
        dim3 g(768/128, MROWS/128, 1);
        gemm_ps<3><<<g, 512, SMEM_GEMM>>>(xps, wps, nullptr, qps, kps, v, nullptr,
                                          DIM, DIM*4, DIM*4, 0, 0);
    }

    // ---- fork 2: V transpose (aux) || scores (main) ----
    cudaEventRecord(evFork2, 0);
    cudaStreamWaitEvent(sAux, evFork2, 0);
    transpose_h<<<dim3(UDIM/32, SEQ/32, BATCH), 256, 0, sAux>>>(v, vth,
        (size_t)SEQ*UDIM, (size_t)UDIM*SEQ*2);
    cudaEventRecord(evJoin2, sAux);

    // scores: writes P_tile fp16 + per-tile stats
    {
        dim3 g(SEQ/128, SEQ/128, BATCH);
        gemm_ps<2><<<g, 512, SMEM_GEMM>>>(qps, kps, ph, nullptr, nullptr, nullptr, part,
                                          UDIM, UDIM*4, UDIM*4,
                                          (size_t)SEQ*UDIM*4, (size_t)SEQ*UDIM*4);
    }

    cudaStreamWaitEvent(0, evJoin2, 0);

    // ---- out = P V, fp16 GEMM with in-prologue shift + fused rescale ----
    {
        dim3 g(UDIM/128, SEQ/128, BATCH);
        gemm_h<<<g, 512, SMEM_H>>>(ph, vth, out, part,
                                   SEQ, SEQ*2, SEQ*2, UDIM,
                                   (size_t)SEQ*SEQ*2, (size_t)UDIM*SEQ*2,
                                   (size_t)SEQ*UDIM);
    }
}

// round 17
// speedup vs baseline: 1.0116x; 1.0116x over previous
#include <cuda_runtime.h>
#include <cuda_bf16.h>
#include <cuda_fp16.h>
#include <math.h>
#include <stdint.h>

#define BATCH 4
#define SEQ   2048
#define DIM   512
#define UDIM  256
#define MROWS (BATCH*SEQ)

// ---------------- scratch (device globals) ---------------------------------
__device__ __align__(128) unsigned char g_xps [(size_t)MROWS*DIM*4];
__device__ __align__(128) unsigned char g_wps [(size_t)3*UDIM*DIM*4];
__device__ __align__(128) unsigned char g_qps [(size_t)MROWS*UDIM*4];
__device__ __align__(128) unsigned char g_kps [(size_t)MROWS*UDIM*4];
__device__ __align__(128) float         g_v   [(size_t)MROWS*UDIM];
__device__ __align__(128) unsigned char g_vth [(size_t)BATCH*UDIM*SEQ*2];  // fp16 [U,S]
__device__ __align__(128) unsigned char g_ph  [(size_t)MROWS*SEQ*2];       // fp16 P (tile-shifted)
__device__ __align__(128) float2        g_part[(size_t)MROWS*16];

// ---------------- helpers ---------------------------------------------------
__device__ __forceinline__ uint32_t smem_u32(const void* p){
    uint32_t a;
    asm("{ .reg .u64 t; cvta.to.shared.u64 t, %1; cvt.u32.u64 %0, t; }" : "=r"(a) : "l"(p));
    return a;
}
__device__ __forceinline__ uint32_t sw128(uint32_t off){ return off ^ ((off>>3)&0x70); }

__device__ __forceinline__ uint32_t packh(float a, float b){
    __half2 h = __floats2half2_rn(a, b);
    return *reinterpret_cast<uint32_t*>(&h);
}
// fp16 limb split: hi = fp16(x), lo = fp16(x - hi)
__device__ __forceinline__ void split2(float a, float b, uint32_t& hi, uint32_t& lo){
    __half ha = __float2half_rn(a), hb = __float2half_rn(b);
    hi = packh(__half2float(ha), __half2float(hb));
    lo = packh(a - __half2float(ha), b - __half2float(hb));
}
__device__ __forceinline__ void split4(float4 v, uint2& hi, uint2& lo){
    split2(v.x, v.y, hi.x, lo.x);
    split2(v.z, v.w, hi.y, lo.y);
}
__device__ __forceinline__ uint32_t hmul2u(uint32_t a, uint32_t b){
    uint32_t r;
    asm("mul.rn.f16x2 %0, %1, %2;" : "=r"(r) : "r"(a), "r"(b));
    return r;
}

// fast exp for x <= 0, FMA/ALU pipes only
__device__ __forceinline__ float fexp(float x){
    float t = x * 1.44269504088896f;
    t = fmaxf(t, -120.f);
    float rn = t + 12582912.f;
    int   ki = (__float_as_int(rn) & 0x7FFFFF) - 0x400000;
    float f  = t - (rn - 12582912.f);
    float p = fmaf(f, 0.00961812910762848f, 0.0555041086648216f);
    p = fmaf(f, p, 0.240226506959101f);
    p = fmaf(f, p, 0.693147180559945f);
    p = fmaf(f, p, 1.0f);
    return __int_as_float(__float_as_int(p) + (ki << 23));
}

__device__ __forceinline__ void cpa16(uint32_t dst, const void* src){
    asm volatile("cp.async.cg.shared.global [%0], [%1], 16;" :: "r"(dst), "l"(src));
}
__device__ __forceinline__ void cpa_commit(){ asm volatile("cp.async.commit_group;" ::: "memory"); }
template<int N> __device__ __forceinline__ void cpa_wait(){
    asm volatile("cp.async.wait_group %0;" :: "n"(N) : "memory");
}
__device__ __forceinline__ void ldm_x4(uint32_t* r, uint32_t addr){
    asm volatile("ldmatrix.sync.aligned.m8n8.x4.shared.b16 {%0,%1,%2,%3}, [%4];"
                 : "=r"(r[0]), "=r"(r[1]), "=r"(r[2]), "=r"(r[3]) : "r"(addr));
}
// fp16 inputs, fp32 accumulator
#define MMA16816H(d, a, b0v, b1v) \
    asm volatile("mma.sync.aligned.m16n8k16.row.col.f32.f16.f16.f32 " \
                 "{%0,%1,%2,%3},{%4,%5,%6,%7},{%8,%9},{%0,%1,%2,%3};" \
                 : "+f"((d)[0]), "+f"((d)[1]), "+f"((d)[2]), "+f"((d)[3]) \
                 : "r"((a)[0]), "r"((a)[1]), "r"((a)[2]), "r"((a)[3]), \
                   "r"(b0v), "r"(b1v))
// fp16 inputs, fp16 accumulator (2 regs = 4 halves)
#define MMA16816HH(d2, a, b0v, b1v) \
    asm volatile("mma.sync.aligned.m16n8k16.row.col.f16.f16.f16.f16 " \
                 "{%0,%1},{%2,%3,%4,%5},{%6,%7},{%0,%1};" \
                 : "+r"((d2)[0]), "+r"((d2)[1]) \
                 : "r"((a)[0]), "r"((a)[1]), "r"((a)[2]), "r"((a)[3]), \
                   "r"(b0v), "r"(b1v))

// ---------------- generic fp16x3 ps GEMM ------------------------------------
// MODE 3: QKV router (V column blocks run single-term). MODE 2: scores.
#define STAGES    4
#define STG_BYTES 16384
#define SMEM_GEMM (STAGES*2*STG_BYTES)   // 128 KB

template<int MODE>
__global__ __launch_bounds__(512)
void gemm_ps(const unsigned char* __restrict__ A, const unsigned char* __restrict__ B,
             unsigned char* __restrict__ Cp, unsigned char* __restrict__ Cq,
             unsigned char* __restrict__ Ck, float* __restrict__ Cv,
             float2* __restrict__ part,
             int K, int pitchA, int pitchB,
             size_t sA, size_t sB)
{
    extern __shared__ char smem[];
    __shared__ float2 stat_sm[4][32][4];
    __shared__ float  m_comb[4][32];
    A += (size_t)blockIdx.z * sA;
    B += (size_t)blockIdx.z * sB;

    const int tid = threadIdx.x;
    const int wid = tid >> 5, lt = tid & 31;
    const int warpM = (wid & 3) * 32, warpN = (wid >> 2) * 32;
    const int rowBase = blockIdx.y * 128, colBase = blockIdx.x * 128;

    // V column blocks (cols >= 512) need only the hi*hi term
    const bool vblk = (MODE == 3) && (blockIdx.x >= 4);

    const int lr = tid >> 2;
    const int lg = (tid & 3) * 32;
    const uint32_t mask = (uint32_t)(lr & 7) * 16;
    const uint32_t o1 = (uint32_t)lr * 128 + ((uint32_t)lg ^ mask);
    const uint32_t o2 = o1 ^ 16;
    const unsigned char* gA = A + (size_t)(rowBase + lr) * pitchA + lg;
    const unsigned char* gB = B + (size_t)(colBase + lr) * pitchB + lg;

    const uint32_t sb = smem_u32(smem);
    const int nch = K / 32;

    const uint32_t aOff = (uint32_t)((warpM + (lt & 15)) * 128 + ((lt >> 4) & 1) * 16);
    const uint32_t bOff = (uint32_t)((warpN + (lt & 7) + ((lt >> 4) & 1) * 8) * 128
                                     + ((lt >> 3) & 1) * 16);

    float acc[2][4][4];
    uint32_t acch[2][4][2];
    #pragma unroll
    for (int i = 0; i < 2; i++)
        #pragma unroll
        for (int j = 0; j < 4; j++) {
            #pragma unroll
            for (int e = 0; e < 4; e++) acc[i][j][e] = 0.f;
            acch[i][j][0] = 0u; acch[i][j][1] = 0u;
        }

    #pragma unroll
    for (int st = 0; st < 3; st++) {
        uint32_t base = sb + (uint32_t)st * (2*STG_BYTES);
        const unsigned char* pa = gA + (size_t)st * 128;
        const unsigned char* pb = gB + (size_t)st * 128;
        cpa16(base + o1, pa);                 cpa16(base + o2, pa + 16);
        cpa16(base + STG_BYTES + o1, pb);     cpa16(base + STG_BYTES + o2, pb + 16);
        cpa_commit();
    }

    for (int c = 0; c < nch; c++) {
        cpa_wait<2>();
        __syncthreads();

        if (c + 3 < nch) {
            uint32_t base = sb + (uint32_t)((c + 3) & 3) * (2*STG_BYTES);
            const unsigned char* pa = gA + (size_t)(c + 3) * 128;
            const unsigned char* pb = gB + (size_t)(c + 3) * 128;
            cpa16(base + o1, pa);                 cpa16(base + o2, pa + 16);
            cpa16(base + STG_BYTES + o1, pb);     cpa16(base + STG_BYTES + o2, pb + 16);
        }
        cpa_commit();

        const uint32_t aB = sb + (uint32_t)(c & 3) * (2*STG_BYTES);
        const uint32_t bB = aB + STG_BYTES;

        #pragma unroll
        for (int s = 0; s < 2; s++) {
            uint32_t ah[2][4], al[2][4], bh[2][4], bl[2][4];
            #pragma unroll
            for (int mt = 0; mt < 2; mt++) {
                uint32_t o = aOff + (uint32_t)mt * 2048 + (uint32_t)s * 32;
                ldm_x4(ah[mt], aB + sw128(o));
            }
            #pragma unroll
            for (int np = 0; np < 2; np++) {
                uint32_t o = bOff + (uint32_t)np * 2048 + (uint32_t)s * 32;
                ldm_x4(bh[np], bB + sw128(o));
            }
            // hi*hi into f32 accumulators (always)
            #pragma unroll
            for (int mt = 0; mt < 2; mt++)
                #pragma unroll
                for (int nt = 0; nt < 4; nt++) {
                    const int np = nt >> 1, ix = (nt & 1) * 2;
                    MMA16816H(acc[mt][nt], ah[mt], bh[np][ix], bh[np][ix+1]);
                }
            // cross terms into f16 accumulators (skip for V column blocks)
            if (!vblk) {
                #pragma unroll
                for (int mt = 0; mt < 2; mt++) {
                    uint32_t o = aOff + (uint32_t)mt * 2048 + (uint32_t)s * 32;
                    ldm_x4(al[mt], aB + sw128(o + 64));
                }
                #pragma unroll
                for (int np = 0; np < 2; np++) {
                    uint32_t o = bOff + (uint32_t)np * 2048 + (uint32_t)s * 32;
                    ldm_x4(bl[np], bB + sw128(o + 64));
                }
                #pragma unroll
                for (int mt = 0; mt < 2; mt++)
                    #pragma unroll
                    for (int nt = 0; nt < 4; nt++) {
                        const int np = nt >> 1, ix = (nt & 1) * 2;
                        MMA16816HH(acch[mt][nt], ah[mt], bl[np][ix], bl[np][ix+1]);
                    }
                #pragma unroll
                for (int mt = 0; mt < 2; mt++)
                    #pragma unroll
                    for (int nt = 0; nt < 4; nt++) {
                        const int np = nt >> 1, ix = (nt & 1) * 2;
                        MMA16816HH(acch[mt][nt], al[mt], bh[np][ix], bh[np][ix+1]);
                    }
            }
        }
    }

    // fold f16 cross-term accumulators into f32 acc
    #pragma unroll
    for (int mt = 0; mt < 2; mt++)
        #pragma unroll
        for (int nt = 0; nt < 4; nt++) {
            float2 c01 = __half22float2(*reinterpret_cast<__half2*>(&acch[mt][nt][0]));
            float2 c23 = __half22float2(*reinterpret_cast<__half2*>(&acch[mt][nt][1]));
            acc[mt][nt][0] += c01.x;  acc[mt][nt][1] += c01.y;
            acc[mt][nt][2] += c23.x;  acc[mt][nt][3] += c23.y;
        }

    if (MODE == 3) {
        #pragma unroll
        for (int mt = 0; mt < 2; mt++) {
            const int r0 = rowBase + warpM + mt * 16 + (lt >> 2);
            #pragma unroll
            for (int nt = 0; nt < 4; nt++) {
                const int col = colBase + warpN + nt * 8 + (lt & 3) * 2;
                if (col < 512) {
                    unsigned char* base = (col < 256) ? Cq : Ck;
                    const int cc = col & 255;
                    const uint32_t cb = (uint32_t)(cc >> 5) * 128 + (uint32_t)(cc & 31) * 2;
                    uint32_t hi, lo;
                    split2(acc[mt][nt][0], acc[mt][nt][1], hi, lo);
                    unsigned char* p0 = base + (size_t)r0 * (UDIM*4) + cb;
                    *(uint32_t*)p0        = hi;
                    *(uint32_t*)(p0 + 64) = lo;
                    split2(acc[mt][nt][2], acc[mt][nt][3], hi, lo);
                    unsigned char* p1 = base + (size_t)(r0 + 8) * (UDIM*4) + cb;
                    *(uint32_t*)p1        = hi;
                    *(uint32_t*)(p1 + 64) = lo;
                } else {
                    const int cc = col - 512;
                    *(float2*)&Cv[(size_t)r0 * UDIM + cc] =
                        make_float2(acc[mt][nt][0], acc[mt][nt][1]);
                    *(float2*)&Cv[(size_t)(r0 + 8) * UDIM + cc] =
                        make_float2(acc[mt][nt][2], acc[mt][nt][3]);
                }
            }
        }
        return;
    }

    if (MODE == 2) {
        // ---- per-(row, warpN-group) stats ----
        #pragma unroll
        for (int mt = 0; mt < 2; mt++) {
            #pragma unroll
            for (int half = 0; half < 2; half++) {
                float m = -INFINITY;
                #pragma unroll
                for (int nt = 0; nt < 4; nt++)
                    m = fmaxf(m, fmaxf(acc[mt][nt][half*2], acc[mt][nt][half*2+1]));
                float l = 0.f;
                #pragma unroll
                for (int nt = 0; nt < 4; nt++) {
                    l += __expf(acc[mt][nt][half*2]   - m);
                    l += __expf(acc[mt][nt][half*2+1] - m);
                }
                #pragma unroll
                for (int off = 1; off <= 2; off <<= 1) {
                    float om = __shfl_xor_sync(0xffffffffu, m, off);
                    float ol = __shfl_xor_sync(0xffffffffu, l, off);
                    float nm = fmaxf(m, om);
                    l = l * __expf(m - nm) + ol * __expf(om - nm);
                    m = nm;
                }
                if ((lt & 3) == 0) {
                    const int rloc = mt * 16 + half * 8 + (lt >> 2);
                    stat_sm[wid & 3][rloc][wid >> 2] = make_float2(m, l);
                }
            }
        }
        __syncthreads();
        if (tid < 128) {
            const int mw = tid >> 5, r = tid & 31;
            float2 a = stat_sm[mw][r][0];
            float m = a.x, l = a.y;
            #pragma unroll
            for (int j = 1; j < 4; j++) {
                float2 b = stat_sm[mw][r][j];
                float nm = fmaxf(m, b.x);
                l = l * __expf(m - nm) + b.y * __expf(b.x - nm);
                m = nm;
            }
            const size_t grow = (size_t)blockIdx.z * SEQ + rowBase + mw * 32 + r;
            part[grow * 16 + blockIdx.x] = make_float2(m, l);
            m_comb[mw][r] = m;
        }
        __syncthreads();

        // ---- write P_tile = exp(s - m_tile) as fp16 ----
        #pragma unroll
        for (int mt = 0; mt < 2; mt++) {
            const int rl0 = mt * 16 + (lt >> 2);
            const float m0 = m_comb[wid & 3][rl0];
            const float m1 = m_comb[wid & 3][rl0 + 8];
            const size_t gr0 = (size_t)blockIdx.z * SEQ + rowBase + warpM + rl0;
            #pragma unroll
            for (int nt = 0; nt < 4; nt++) {
                const int col = colBase + warpN + nt * 8 + (lt & 3) * 2;
                *(uint32_t*)(Cp + gr0 * (SEQ*2) + (size_t)col * 2) =
                    packh(fexp(acc[mt][nt][0] - m0), fexp(acc[mt][nt][1] - m0));
                *(uint32_t*)(Cp + (gr0 + 8) * (SEQ*2) + (size_t)col * 2) =
                    packh(fexp(acc[mt][nt][2] - m1), fexp(acc[mt][nt][3] - m1));
            }
        }
    }
}

// ---------------- fp16 PV GEMM with in-prologue shift + fused rescale -------
#define SCL_OFF   (STAGES*2*STG_BYTES)          // after the 128 KB stage ring
#define SMEM_H    (SCL_OFF + 128*17*4)          // + padded scale table (8.5 KB)

__global__ __launch_bounds__(512)
void gemm_h(const unsigned char* __restrict__ A, const unsigned char* __restrict__ B,
            float* __restrict__ C, const float2* __restrict__ part,
            int K, int pitchA, int pitchB, int ldC,
            size_t sA, size_t sB, size_t sC)
{
    extern __shared__ char smem[];
    A += (size_t)blockIdx.z * sA;
    B += (size_t)blockIdx.z * sB;
    C += (size_t)blockIdx.z * sC;
    part += (size_t)blockIdx.z * SEQ * 16;

    const int tid = threadIdx.x;
    const int wid = tid >> 5, lt = tid & 31;
    const int warpM = (wid & 3) * 32, warpN = (wid >> 2) * 32;
    const int rowBase = blockIdx.y * 128, colBase = blockIdx.x * 128;

    const int lr = tid >> 2;
    const int lg = (tid & 3) * 32;
    const uint32_t mask = (uint32_t)(lr & 7) * 16;
    const uint32_t o1 = (uint32_t)lr * 128 + ((uint32_t)lg ^ mask);
    const uint32_t o2 = o1 ^ 16;
    const unsigned char* gA = A + (size_t)(rowBase + lr) * pitchA + lg;
    const unsigned char* gB = B + (size_t)(colBase + lr) * pitchB + lg;

    const uint32_t sb = smem_u32(smem);
    const int nch = K / 64;

    const uint32_t aOff = (uint32_t)((warpM + (lt & 15)) * 128 + ((lt >> 4) & 1) * 16);
    const uint32_t bOff = (uint32_t)((warpN + (lt & 7) + ((lt >> 4) & 1) * 8) * 128
                                     + ((lt >> 3) & 1) * 16);

    float acc[2][4][4];
    #pragma unroll
    for (int i = 0; i < 2; i++)
        #pragma unroll
        for (int j = 0; j < 4; j++)
            #pragma unroll
            for (int e = 0; e < 4; e++) acc[i][j][e] = 0.f;

    #pragma unroll
    for (int st = 0; st < 3; st++) {
        uint32_t base = sb + (uint32_t)st * (2*STG_BYTES);
        const unsigned char* pa = gA + (size_t)st * 128;
        const unsigned char* pb = gB + (size_t)st * 128;
        cpa16(base + o1, pa);                 cpa16(base + o2, pa + 16);
        cpa16(base + STG_BYTES + o1, pb);     cpa16(base + STG_BYTES + o2, pb + 16);
        cpa_commit();
    }

    // ---- in-prologue shift + scale table (overlaps cp.async latency) ----
    {
        const int r = tid >> 2, q = tid & 3;
        const float2* pp = part + ((size_t)rowBase + r) * 16 + q * 4;
        float2 p0 = pp[0], p1 = pp[1], p2 = pp[2], p3 = pp[3];
        float m = fmaxf(fmaxf(p0.x, p1.x), fmaxf(p2.x, p3.x));
        m = fmaxf(m, __shfl_xor_sync(0xffffffffu, m, 1));
        m = fmaxf(m, __shfl_xor_sync(0xffffffffu, m, 2));
        float l = p0.y * __expf(p0.x - m) + p1.y * __expf(p1.x - m)
                + p2.y * __expf(p2.x - m) + p3.y * __expf(p3.x - m);
        l += __shfl_xor_sync(0xffffffffu, l, 1);
        l += __shfl_xor_sync(0xffffffffu, l, 2);
        const float sh = m + logf(l);
        float* srow = (float*)(smem + SCL_OFF) + r * 17 + q * 4;
        srow[0] = __expf(p0.x - sh);
        srow[1] = __expf(p1.x - sh);
        srow[2] = __expf(p2.x - sh);
        srow[3] = __expf(p3.x - sh);
    }

    uint32_t scl2[4];   // half2 broadcast scales: rows +0, +8, +16, +24

    for (int c = 0; c < nch; c++) {
        cpa_wait<2>();
        __syncthreads();   // also orders the scale-table writes (at c==0)

        if ((c & 1) == 0) {
            const int t = c >> 1;
            const float* ss = (const float*)(smem + SCL_OFF);
            const int rb = warpM + (lt >> 2);
            float f0  = ss[(rb +  0) * 17 + t];
            float f8  = ss[(rb +  8) * 17 + t];
            float f16 = ss[(rb + 16) * 17 + t];
            float f24 = ss[(rb + 24) * 17 + t];
            scl2[0] = packh(f0,  f0);
            scl2[1] = packh(f8,  f8);
            scl2[2] = packh(f16, f16);
            scl2[3] = packh(f24, f24);
        }

        if (c + 3 < nch) {
            uint32_t base = sb + (uint32_t)((c + 3) & 3) * (2*STG_BYTES);
            const unsigned char* pa = gA + (size_t)(c + 3) * 128;
            const unsigned char* pb = gB + (size_t)(c + 3) * 128;
            cpa16(base + o1, pa);                 cpa16(base + o2, pa + 16);
            cpa16(base + STG_BYTES + o1, pb);     cpa16(base + STG_BYTES + o2, pb + 16);
        }
        cpa_commit();

        const uint32_t aB = sb + (uint32_t)(c & 3) * (2*STG_BYTES);
        const uint32_t bB = aB + STG_BYTES;

        #pragma unroll
        for (int s = 0; s < 4; s++) {
            uint32_t ah[2][4], bh[2][4];
            #pragma unroll
            for (int mt = 0; mt < 2; mt++) {
                uint32_t o = aOff + (uint32_t)mt * 2048 + (uint32_t)s * 32;
                ldm_x4(ah[mt], aB + sw128(o));
                ah[mt][0] = hmul2u(ah[mt][0], scl2[mt*2]);
                ah[mt][2] = hmul2u(ah[mt][2], scl2[mt*2]);
                ah[mt][1] = hmul2u(ah[mt][1], scl2[mt*2+1]);
                ah[mt][3] = hmul2u(ah[mt][3], scl2[mt*2+1]);
            }
            #pragma unroll
            for (int np = 0; np < 2; np++) {
                uint32_t o = bOff + (uint32_t)np * 2048 + (uint32_t)s * 32;
                ldm_x4(bh[np], bB + sw128(o));
            }
            #pragma unroll
            for (int mt = 0; mt < 2; mt++)
                #pragma unroll
                for (int nt = 0; nt < 4; nt++) {
                    const int np = nt >> 1, ix = (nt & 1) * 2;
                    MMA16816H(acc[mt][nt], ah[mt], bh[np][ix], bh[np][ix+1]);
                }
        }
    }

    #pragma unroll
    for (int mt = 0; mt < 2; mt++) {
        const int r0 = rowBase + warpM + mt * 16 + (lt >> 2);
        #pragma unroll
        for (int nt = 0; nt < 4; nt++) {
            const int cc = colBase + warpN + nt * 8 + (lt & 3) * 2;
            *(float2*)&C[(size_t)r0 * ldC + cc] =
                make_float2(acc[mt][nt][0], acc[mt][nt][1]);
            *(float2*)&C[(size_t)(r0 + 8) * ldC + cc] =
                make_float2(acc[mt][nt][2], acc[mt][nt][3]);
        }
    }
}

// ---------------- split fp32 -> packed-split fp16 limbs ---------------------
__global__ __launch_bounds__(256)
void split_pack(const float* __restrict__ in, unsigned char* __restrict__ out, int Kelems)
{
    const size_t idx = ((size_t)blockIdx.x * 256 + threadIdx.x) * 8;
    const size_t row = idx / Kelems;
    const int k0 = (int)(idx % Kelems);
    float4 f0 = *(const float4*)(in + idx);
    float4 f1 = *(const float4*)(in + idx + 4);
    uint2 h0, l0, h1, l1;
    split4(f0, h0, l0);
    split4(f1, h1, l1);
    unsigned char* p = out + row * ((size_t)Kelems * 4) + (k0 >> 5) * 128 + (k0 & 31) * 2;
    *(uint4*)p        = make_uint4(h0.x, h0.y, h1.x, h1.y);
    *(uint4*)(p + 64) = make_uint4(l0.x, l0.y, l1.x, l1.y);
}

// ---------------- fused 3-weight transpose+split (fp16 limbs) ---------------
__global__ __launch_bounds__(256)
void transpose_split_w(const float* __restrict__ W0, const float* __restrict__ W1,
                       const float* __restrict__ W2, unsigned char* __restrict__ out)
{
    __shared__ float t[32][33];
    const float* in = (blockIdx.z == 0) ? W0 : (blockIdx.z == 1) ? W1 : W2;
    out += (size_t)blockIdx.z * ((size_t)UDIM * DIM * 4);
    const int tid = threadIdx.x;
    const int tx = tid & 31, ty = tid >> 5;
    int x = blockIdx.x * 32 + tx;
    int y = blockIdx.y * 32 + ty;
    #pragma unroll
    for (int j = 0; j < 32; j += 8)
        t[ty + j][tx] = in[(size_t)(y + j) * UDIM + x];
    __syncthreads();

    const int wr = tid >> 3;
    const int wg = tid & 7;
    uint32_t h0, l0, h1, l1;
    split2(t[wg*4 + 0][wr], t[wg*4 + 1][wr], h0, l0);
    split2(t[wg*4 + 2][wr], t[wg*4 + 3][wr], h1, l1);
    unsigned char* p = out + (size_t)(blockIdx.x * 32 + wr) * (DIM*4)
                           + (size_t)blockIdx.y * 128 + wg * 8;
    *(uint2*)p        = make_uint2(h0, h1);
    *(uint2*)(p + 64) = make_uint2(l0, l1);
}

// ---------------- V transpose: fp32 [S,U] -> fp16 [U,S] ---------------------
__global__ __launch_bounds__(256)
void transpose_h(const float* __restrict__ in, unsigned char* __restrict__ out,
                 size_t sIn, size_t sOut)
{
    __shared__ float t[32][33];
    in  += (size_t)blockIdx.z * sIn;
    out += (size_t)blockIdx.z * sOut;
    const int tid = threadIdx.x;
    const int tx = tid & 31, ty = tid >> 5;
    int x = blockIdx.x * 32 + tx;
    int y = blockIdx.y * 32 + ty;
    #pragma unroll
    for (int j = 0; j < 32; j += 8)
        t[ty + j][tx] = in[(size_t)(y + j) * UDIM + x];
    __syncthreads();

    const int wr = tid >> 3;
    const int wg = tid & 7;
    uint32_t h01 = packh(t[wg*4 + 0][wr], t[wg*4 + 1][wr]);
    uint32_t h23 = packh(t[wg*4 + 2][wr], t[wg*4 + 3][wr]);
    unsigned char* p = out + (size_t)(blockIdx.x * 32 + wr) * (SEQ*2)
                           + (size_t)blockIdx.y * 64 + wg * 8;
    *(uint2*)p = make_uint2(h01, h23);
}

// ---------------- launch ----------------------------------------------------
extern "C" void kernel_launch(void* const* d_in, const int* in_sizes, int n_in,
                              void* d_out, int out_size)
{
    const float* x  = (const float*)d_in[0];
    const float* Wq = (const float*)d_in[1];
    const float* Wk = (const float*)d_in[2];
    const float* Wv = (const float*)d_in[3];
    float* out = (float*)d_out;

    unsigned char *xps, *wps, *qps, *kps, *vth, *ph;
    float *v;
    float2 *part;
    cudaGetSymbolAddress((void**)&xps,  g_xps);
    cudaGetSymbolAddress((void**)&wps,  g_wps);
    cudaGetSymbolAddress((void**)&qps,  g_qps);
    cudaGetSymbolAddress((void**)&kps,  g_kps);
    cudaGetSymbolAddress((void**)&v,    g_v);
    cudaGetSymbolAddress((void**)&vth,  g_vth);
    cudaGetSymbolAddress((void**)&ph,   g_ph);
    cudaGetSymbolAddress((void**)&part, g_part);

    cudaFuncSetAttribute(gemm_ps<2>, cudaFuncAttributeMaxDynamicSharedMemorySize, SMEM_GEMM);
    cudaFuncSetAttribute(gemm_ps<3>, cudaFuncAttributeMaxDynamicSharedMemorySize, SMEM_GEMM);
    cudaFuncSetAttribute(gemm_h,     cudaFuncAttributeMaxDynamicSharedMemorySize, SMEM_H);

    static cudaStream_t sAux = nullptr;
    static cudaEvent_t evFork1 = nullptr, evJoin1 = nullptr,
                       evFork2 = nullptr, evJoin2 = nullptr;
    if (sAux == nullptr) {
        cudaStreamCreateWithFlags(&sAux, cudaStreamNonBlocking);
        cudaEventCreateWithFlags(&evFork1, cudaEventDisableTiming);
        cudaEventCreateWithFlags(&evJoin1, cudaEventDisableTiming);
        cudaEventCreateWithFlags(&evFork2, cudaEventDisableTiming);
        cudaEventCreateWithFlags(&evJoin2, cudaEventDisableTiming);
    }

    // ---- fork 1: weight prep (aux) || x split (main) ----
    cudaEventRecord(evFork1, 0);
    cudaStreamWaitEvent(sAux, evFork1, 0);
    transpose_split_w<<<dim3(UDIM/32, DIM/32, 3), 256, 0, sAux>>>(Wq, Wk, Wv, wps);
    cudaEventRecord(evJoin1, sAux);

    split_pack<<<(MROWS*DIM)/(256*8), 256>>>(x, xps, DIM);
    cudaStreamWaitEvent(0, evJoin1, 0);

    // ---- fused QKV with router epilogue; V columns single-term ----
    {
        dim3 g(768/128, MROWS/128, 1);
        gemm_ps<3><<<g, 512, SMEM_GEMM>>>(xps, wps, nullptr, qps, kps, v, nullptr,
                                          DIM, DIM*4, DIM*4, 0, 0);
    }

    // ---- fork 2: V transpose (aux) || scores (main) ----
    cudaEventRecord(evFork2, 0);
    cudaStreamWaitEvent(sAux, evFork2, 0);
    transpose_h<<<dim3(UDIM/32, SEQ/32, BATCH), 256, 0, sAux>>>(v, vth,
        (size_t)SEQ*UDIM, (size_t)UDIM*SEQ*2);
    cudaEventRecord(evJoin2, sAux);

    // scores: writes P_tile fp16 + per-tile stats
    {
        dim3 g(SEQ/128, SEQ/128, BATCH);
        gemm_ps<2><<<g, 512, SMEM_GEMM>>>(qps, kps, ph, nullptr, nullptr, nullptr, part,
                                          UDIM, UDIM*4, UDIM*4,
                                          (size_t)SEQ*UDIM*4, (size_t)SEQ*UDIM*4);
    }

    cudaStreamWaitEvent(0, evJoin2, 0);

    // ---- out = P V, fp16 GEMM with in-prologue shift + fused rescale ----
    {
        dim3 g(UDIM/128, SEQ/128, BATCH);
        gemm_h<<<g, 512, SMEM_H>>>(ph, vth, out, part,
                                   SEQ, SEQ*2, SEQ*2, UDIM,
                                   (size_t)SEQ*SEQ*2, (size_t)UDIM*SEQ*2,
                                   (size_t)SEQ*UDIM);
    }
}